// round 1
// baseline (speedup 1.0000x reference)
#include <cuda_runtime.h>
#include <math.h>

// Problem constants
#define B_ 8
#define S_ 2048
#define H_ 768
#define NSP 512
#define NROW (B_ * NSP)          // 4096 span rows
#define SPAN_DIM 2688            // 3*H + H/2
#define SIN_DIM 2706             // SPAN_DIM + 18
#define LDR 2720                 // padded row stride for rep/s_in scratch (mult of 4, > 2706)
#define N_TYPE 18
#define N_SENS 4
#define N_BIO 3
#define WEMB_D 384               // H/2

// Scratch (static device globals are zero-initialized; pad cols [2706,2720) stay 0 forever)
__device__ float g_rep[(size_t)NROW * LDR];   // rep ++ type_probs ++ zero pad
__device__ float g_t[(size_t)NROW * H_];      // gelu(rep @ W_t1 + b)
__device__ float g_s[(size_t)NROW * H_];      // gelu(s_in @ W_s1 + b)

__device__ __forceinline__ float gelu_exact(float x) {
    return 0.5f * x * (1.0f + erff(x * 0.70710678118654752f));
}

// ---------------------------------------------------------------------------
// Kernel 1: proposal_logits = hidden @ W_prop + b  ([B*S,768] x [768,3])
// one warp per row, W_prop staged in shared
// ---------------------------------------------------------------------------
__global__ void proposal_kernel(const float* __restrict__ hidden,
                                const float* __restrict__ W_prop,
                                const float* __restrict__ b_prop,
                                float* __restrict__ out) {
    __shared__ float sW[H_ * N_BIO];
    for (int i = threadIdx.x; i < H_ * N_BIO; i += blockDim.x) sW[i] = W_prop[i];
    __syncthreads();

    int warp = threadIdx.x >> 5;
    int lane = threadIdx.x & 31;
    int row = blockIdx.x * 8 + warp;          // 8 warps/block
    if (row >= B_ * S_) return;

    const float* h = hidden + (size_t)row * H_;
    float a0 = 0.f, a1 = 0.f, a2 = 0.f;
    for (int j = lane; j < H_; j += 32) {
        float hv = h[j];
        a0 += hv * sW[j * 3 + 0];
        a1 += hv * sW[j * 3 + 1];
        a2 += hv * sW[j * 3 + 2];
    }
    #pragma unroll
    for (int off = 16; off; off >>= 1) {
        a0 += __shfl_xor_sync(0xffffffffu, a0, off);
        a1 += __shfl_xor_sync(0xffffffffu, a1, off);
        a2 += __shfl_xor_sync(0xffffffffu, a2, off);
    }
    if (lane == 0) {
        out[row * 3 + 0] = a0 + b_prop[0];
        out[row * 3 + 1] = a1 + b_prop[1];
        out[row * 3 + 2] = a2 + b_prop[2];
    }
}

// ---------------------------------------------------------------------------
// Kernel 2: build span representations into g_rep (one block per span)
// rep = [start_h(768) | end_h(768) | pooled(768) | width_emb(384)]
// ---------------------------------------------------------------------------
__global__ void span_rep_kernel(const float* __restrict__ hidden,
                                const int* __restrict__ spans,
                                const float* __restrict__ width_emb) {
    int row = blockIdx.x;                   // 0..4095
    int b = row >> 9;
    int s = spans[row * 2 + 0];
    int e = spans[row * 2 + 1];
    int w = e - s + 1;
    float inv_w = 1.0f / (float)w;
    const float* hb = hidden + (size_t)b * S_ * H_;
    float* r = g_rep + (size_t)row * LDR;

    for (int i = threadIdx.x; i < H_; i += blockDim.x) {
        r[i]        = hb[(size_t)s * H_ + i];
        r[H_ + i]   = hb[(size_t)e * H_ + i];
        float acc = 0.f;
        for (int q = s; q <= e; q++) acc += hb[(size_t)q * H_ + i];
        r[2 * H_ + i] = acc * inv_w;
    }
    int wc = w < 63 ? w : 63;
    for (int i = threadIdx.x; i < WEMB_D; i += blockDim.x)
        r[3 * H_ + i] = width_emb[wc * WEMB_D + i];
}

// ---------------------------------------------------------------------------
// Kernel 3/5: fp32 tiled GEMM with fused bias + exact GELU
// C[M,N] = gelu(A[M,K](lda) * B[K,N](ldb) + bias)
// BM=128 BN=64 BK=16, 256 threads, 8x4 microtile
// A may be read up to lda on the K axis (pad region must be zero); B is
// guarded for k >= K.
// ---------------------------------------------------------------------------
#define BM 128
#define BN 64
#define BK 16

__global__ __launch_bounds__(256)
void gemm_bias_gelu(const float* __restrict__ A, int lda, int K,
                    const float* __restrict__ B, int ldb,
                    const float* __restrict__ bias,
                    float* __restrict__ C, int ldc) {
    __shared__ float As[BK][BM];
    __shared__ float Bs[BK][BN];

    int tid = threadIdx.x;
    int m0 = blockIdx.y * BM;
    int n0 = blockIdx.x * BN;
    int tx = tid & 15;          // 0..15 -> 4 cols each
    int ty = tid >> 4;          // 0..15 -> 8 rows each

    int arow = tid >> 2;        // 0..63 (two passes -> 128 rows)
    int akf  = tid & 3;         // float4 index within BK
    int brow = tid >> 4;        // 0..15
    int bcol = (tid & 15) * 4;

    float acc[8][4];
    #pragma unroll
    for (int i = 0; i < 8; i++)
        #pragma unroll
        for (int j = 0; j < 4; j++) acc[i][j] = 0.f;

    for (int k0 = 0; k0 < K; k0 += BK) {
        // A tile -> As (transposed store)
        #pragma unroll
        for (int p = 0; p < 2; p++) {
            int r = arow + p * 64;
            const float4 v = *(const float4*)(A + (size_t)(m0 + r) * lda + k0 + akf * 4);
            As[akf * 4 + 0][r] = v.x;
            As[akf * 4 + 1][r] = v.y;
            As[akf * 4 + 2][r] = v.z;
            As[akf * 4 + 3][r] = v.w;
        }
        // B tile -> Bs (guard K tail)
        {
            int kk = k0 + brow;
            float4 v = make_float4(0.f, 0.f, 0.f, 0.f);
            if (kk < K) v = *(const float4*)(B + (size_t)kk * ldb + n0 + bcol);
            *(float4*)&Bs[brow][bcol] = v;
        }
        __syncthreads();

        #pragma unroll
        for (int k = 0; k < BK; k++) {
            float4 a0 = *(const float4*)&As[k][ty * 8];
            float4 a1 = *(const float4*)&As[k][ty * 8 + 4];
            float4 b0 = *(const float4*)&Bs[k][tx * 4];
            float av[8] = {a0.x, a0.y, a0.z, a0.w, a1.x, a1.y, a1.z, a1.w};
            float bv[4] = {b0.x, b0.y, b0.z, b0.w};
            #pragma unroll
            for (int i = 0; i < 8; i++)
                #pragma unroll
                for (int j = 0; j < 4; j++)
                    acc[i][j] = fmaf(av[i], bv[j], acc[i][j]);
        }
        __syncthreads();
    }

    #pragma unroll
    for (int i = 0; i < 8; i++) {
        int row = m0 + ty * 8 + i;
        #pragma unroll
        for (int j = 0; j < 4; j++) {
            int col = n0 + tx * 4 + j;
            float v = acc[i][j] + bias[col];
            C[(size_t)row * ldc + col] = gelu_exact(v);
        }
    }
}

// ---------------------------------------------------------------------------
// Kernel 4: type head. logits = t @ W_t2 + b (18), softmax -> probs into
// g_rep cols [2688,2706); logits to out. one warp per row.
// ---------------------------------------------------------------------------
__global__ void type_head_kernel(const float* __restrict__ W_t2,
                                 const float* __restrict__ b_t2,
                                 float* __restrict__ out_logits) {
    int warp = threadIdx.x >> 5;
    int lane = threadIdx.x & 31;
    int row = blockIdx.x * 8 + warp;
    if (row >= NROW) return;

    const float* t = g_t + (size_t)row * H_;
    float acc[N_TYPE];
    #pragma unroll
    for (int c = 0; c < N_TYPE; c++) acc[c] = 0.f;
    for (int j = lane; j < H_; j += 32) {
        float tv = t[j];
        const float* wrow = W_t2 + j * N_TYPE;
        #pragma unroll
        for (int c = 0; c < N_TYPE; c++) acc[c] = fmaf(tv, wrow[c], acc[c]);
    }
    #pragma unroll
    for (int c = 0; c < N_TYPE; c++)
        #pragma unroll
        for (int off = 16; off; off >>= 1)
            acc[c] += __shfl_xor_sync(0xffffffffu, acc[c], off);

    if (lane == 0) {
        float logit[N_TYPE];
        float mx = -1e30f;
        #pragma unroll
        for (int c = 0; c < N_TYPE; c++) {
            logit[c] = acc[c] + b_t2[c];
            mx = fmaxf(mx, logit[c]);
        }
        float sum = 0.f;
        float ex[N_TYPE];
        #pragma unroll
        for (int c = 0; c < N_TYPE; c++) { ex[c] = expf(logit[c] - mx); sum += ex[c]; }
        float inv = 1.0f / sum;
        float* pr = g_rep + (size_t)row * LDR + SPAN_DIM;
        #pragma unroll
        for (int c = 0; c < N_TYPE; c++) {
            out_logits[row * N_TYPE + c] = logit[c];
            pr[c] = ex[c] * inv;
        }
    }
}

// ---------------------------------------------------------------------------
// Kernel 6: sensitivity head. logits = s @ W_s2 + b (4). one warp per row.
// ---------------------------------------------------------------------------
__global__ void sens_head_kernel(const float* __restrict__ W_s2,
                                 const float* __restrict__ b_s2,
                                 float* __restrict__ out_logits) {
    int warp = threadIdx.x >> 5;
    int lane = threadIdx.x & 31;
    int row = blockIdx.x * 8 + warp;
    if (row >= NROW) return;

    const float* s = g_s + (size_t)row * H_;
    float acc[N_SENS];
    #pragma unroll
    for (int c = 0; c < N_SENS; c++) acc[c] = 0.f;
    for (int j = lane; j < H_; j += 32) {
        float sv = s[j];
        const float* wrow = W_s2 + j * N_SENS;
        #pragma unroll
        for (int c = 0; c < N_SENS; c++) acc[c] = fmaf(sv, wrow[c], acc[c]);
    }
    #pragma unroll
    for (int c = 0; c < N_SENS; c++)
        #pragma unroll
        for (int off = 16; off; off >>= 1)
            acc[c] += __shfl_xor_sync(0xffffffffu, acc[c], off);

    if (lane == 0) {
        #pragma unroll
        for (int c = 0; c < N_SENS; c++)
            out_logits[row * N_SENS + c] = acc[c] + b_s2[c];
    }
}

// ---------------------------------------------------------------------------
// Launch
// Inputs (metadata order):
// 0 hidden [8,2048,768] f32      1 candidate_spans [8,512,2] i32
// 2 width_emb [64,384]           3 W_prop [768,3]     4 b_prop [3]
// 5 W_t1 [2688,768]              6 b_t1 [768]
// 7 W_t2 [768,18]                8 b_t2 [18]
// 9 W_s1 [2706,768]             10 b_s1 [768]
// 11 W_s2 [768,4]               12 b_s2 [4]
// Output: proposal_logits(49152) ++ type_logits(73728) ++ sens_logits(16384)
// ---------------------------------------------------------------------------
extern "C" void kernel_launch(void* const* d_in, const int* in_sizes, int n_in,
                              void* d_out, int out_size) {
    const float* hidden    = (const float*)d_in[0];
    const int*   spans     = (const int*)d_in[1];
    const float* width_emb = (const float*)d_in[2];
    const float* W_prop    = (const float*)d_in[3];
    const float* b_prop    = (const float*)d_in[4];
    const float* W_t1      = (const float*)d_in[5];
    const float* b_t1      = (const float*)d_in[6];
    const float* W_t2      = (const float*)d_in[7];
    const float* b_t2      = (const float*)d_in[8];
    const float* W_s1      = (const float*)d_in[9];
    const float* b_s1      = (const float*)d_in[10];
    const float* W_s2      = (const float*)d_in[11];
    const float* b_s2      = (const float*)d_in[12];

    float* out_prop = (float*)d_out;                       // 8*2048*3
    float* out_type = out_prop + (size_t)B_ * S_ * N_BIO;  // 8*512*18
    float* out_sens = out_type + (size_t)NROW * N_TYPE;    // 8*512*4

    float* rep_base; cudaGetSymbolAddress((void**)&rep_base, g_rep);
    float* t_base;   cudaGetSymbolAddress((void**)&t_base, g_t);
    float* s_base;   cudaGetSymbolAddress((void**)&s_base, g_s);

    // 1. proposal head
    proposal_kernel<<<(B_ * S_) / 8, 256>>>(hidden, W_prop, b_prop, out_prop);

    // 2. span representations
    span_rep_kernel<<<NROW, 256>>>(hidden, spans, width_emb);

    // 3. t = gelu(rep @ W_t1 + b_t1)
    {
        dim3 grid(H_ / BN, NROW / BM);
        gemm_bias_gelu<<<grid, 256>>>(rep_base, LDR, SPAN_DIM, W_t1, H_, b_t1,
                                      t_base, H_);
    }

    // 4. type logits + softmax (probs appended to rep rows)
    type_head_kernel<<<NROW / 8, 256>>>(W_t2, b_t2, out_type);

    // 5. s = gelu(s_in @ W_s1 + b_s1)   (s_in = rep ++ probs, K = 2706)
    {
        dim3 grid(H_ / BN, NROW / BM);
        gemm_bias_gelu<<<grid, 256>>>(rep_base, LDR, SIN_DIM, W_s1, H_, b_s1,
                                      s_base, H_);
    }

    // 6. sensitivity logits
    sens_head_kernel<<<NROW / 8, 256>>>(W_s2, b_s2, out_sens);
}

// round 3
// speedup vs baseline: 2.5019x; 2.5019x over previous
#include <cuda_runtime.h>
#include <cuda_bf16.h>
#include <math.h>
#include <stdint.h>

// Problem constants
#define B_ 8
#define S_ 2048
#define H_ 768
#define NROW 4096                 // B_ * 512 span rows
#define SPAN_DIM 2688             // 3*H + H/2
#define SIN_DIM 2706              // SPAN_DIM + 18
#define KPAD 2752                 // K padded to multiple of 64
#define N_TYPE 18
#define N_SENS 4
#define N_BIO 3
#define WEMB_D 384

#define KITERS1 42                // 2688/64  (GEMM1: rep only)
#define KITERS2 43                // 2752/64  (GEMM2: rep + probs + zero pad)

// ---------------------------------------------------------------------------
// Static scratch (zero-initialized; pad regions never written -> stay zero)
// ---------------------------------------------------------------------------
__device__ __nv_bfloat16 g_Ahi[(size_t)NROW * KPAD];   // span reps, hi part
__device__ __nv_bfloat16 g_Alo[(size_t)NROW * KPAD];   // span reps, lo part
__device__ __nv_bfloat16 g_Bt1hi[(size_t)H_ * KPAD];   // W_t1^T hi  [768][KPAD]
__device__ __nv_bfloat16 g_Bt1lo[(size_t)H_ * KPAD];
__device__ __nv_bfloat16 g_Bs1hi[(size_t)H_ * KPAD];   // W_s1^T hi
__device__ __nv_bfloat16 g_Bs1lo[(size_t)H_ * KPAD];
__device__ float g_t[(size_t)NROW * H_];               // gelu(rep @ W_t1 + b)
__device__ float g_s[(size_t)NROW * H_];               // gelu(s_in @ W_s1 + b)

__device__ __forceinline__ float gelu_exact(float x) {
    return 0.5f * x * (1.0f + erff(x * 0.70710678118654752f));
}

__device__ __forceinline__ void bsplit(float a, __nv_bfloat16* hi, __nv_bfloat16* lo) {
    __nv_bfloat16 h = __float2bfloat16(a);
    *hi = h;
    *lo = __float2bfloat16(a - __bfloat162float(h));
}

__device__ __forceinline__ uint32_t smem_u32(const void* p) {
    uint32_t a;
    asm("{ .reg .u64 t; cvta.to.shared.u64 t, %1; cvt.u32.u64 %0, t; }" : "=r"(a) : "l"(p));
    return a;
}

__device__ __forceinline__ void cp_async16(uint32_t dst, const void* src) {
    asm volatile("cp.async.cg.shared.global [%0], [%1], 16;" :: "r"(dst), "l"(src) : "memory");
}
#define CP_COMMIT() asm volatile("cp.async.commit_group;" ::: "memory")
#define CP_WAIT(n)  asm volatile("cp.async.wait_group %0;" :: "n"(n) : "memory")

__device__ __forceinline__ void ldmx4(uint32_t* r, uint32_t addr) {
    asm volatile("ldmatrix.sync.aligned.m8n8.x4.shared.b16 {%0,%1,%2,%3}, [%4];"
                 : "=r"(r[0]), "=r"(r[1]), "=r"(r[2]), "=r"(r[3]) : "r"(addr));
}

__device__ __forceinline__ void mma_bf16(float* c, const uint32_t* a, const uint32_t* b) {
    asm volatile(
        "mma.sync.aligned.m16n8k16.row.col.f32.bf16.bf16.f32 "
        "{%0,%1,%2,%3}, {%4,%5,%6,%7}, {%8,%9}, {%0,%1,%2,%3};"
        : "+f"(c[0]), "+f"(c[1]), "+f"(c[2]), "+f"(c[3])
        : "r"(a[0]), "r"(a[1]), "r"(a[2]), "r"(a[3]), "r"(b[0]), "r"(b[1]));
}

// ---------------------------------------------------------------------------
// HMMA GEMM: C[4096,768] = gelu(A * B^T + bias), bf16x3 split, fp32 accum.
// A (Ahi/Alo) bf16 [4096][KPAD]; B^T (Bhi/Blo) bf16 [768][KPAD].
// CTA tile 128x64, BK=64, 4-stage cp.async pipeline, 128 threads.
// SW128-style swizzle: 16B chunk j at row r stored at chunk (j ^ (r&7)).
// ---------------------------------------------------------------------------
#define BMg 128
#define BNg 64
#define GSTAGES 4
#define STG_A_OFF 16384                 // B tile offset within a stage
#define STG_BYTES 24576                 // 16KB A + 8KB B
#define GEMM_SMEM (GSTAGES * STG_BYTES) // 96KB

__global__ __launch_bounds__(128)
void mma_gemm(const __nv_bfloat16* __restrict__ Ahi,
              const __nv_bfloat16* __restrict__ Alo,
              const __nv_bfloat16* __restrict__ Bhi,
              const __nv_bfloat16* __restrict__ Blo,
              const float* __restrict__ bias,
              float* __restrict__ C,
              int kiters) {
    extern __shared__ char smem[];
    const uint32_t sb = smem_u32(smem);
    const int tid = threadIdx.x;
    const int lane = tid & 31;
    const int wid = tid >> 5;
    const int warpM = wid >> 1;            // 0..1 -> 64 rows each
    const int warpN = wid & 1;             // 0..1 -> 32 cols each
    const int m0 = blockIdx.y * BMg;
    const int n0 = blockIdx.x * BNg;
    const int total = 3 * kiters;

    // ---- loader per-thread indices ----
    const int jA = tid & 7;                // 16B chunk within 128B row
    const int r0 = tid >> 3;               // 0..15
    uint32_t dstA[8], dstB[4];
    #pragma unroll
    for (int q = 0; q < 8; q++) {
        int r = r0 + 16 * q;
        dstA[q] = r * 128 + ((jA ^ (r & 7)) << 4);
    }
    #pragma unroll
    for (int q = 0; q < 4; q++) {
        int r = r0 + 16 * q;
        dstB[q] = STG_A_OFF + r * 128 + ((jA ^ (r & 7)) << 4);
    }

    // ---- ldmatrix per-lane row bases ----
    // A x4: lanes 0-7 m0-7/k0, 8-15 m8-15/k0, 16-23 m0-7/k1, 24-31 m8-15/k1
    uint32_t aRowOff[4]; int aR7[4];
    const int csA = lane >> 4;
    #pragma unroll
    for (int mt = 0; mt < 4; mt++) {
        int row = warpM * 64 + mt * 16 + (lane & 7) + ((lane >> 3) & 1) * 8;
        aRowOff[mt] = row * 128;
        aR7[mt] = row & 7;
    }
    // B x4: lanes 0-7 n0-7/k0, 8-15 n0-7/k1, 16-23 n8-15/k0, 24-31 n8-15/k1
    uint32_t bRowOff[2]; int bR7[2];
    const int csB = (lane >> 3) & 1;
    #pragma unroll
    for (int np = 0; np < 2; np++) {
        int n = warpN * 32 + np * 16 + (lane & 7) + ((lane >> 4) & 1) * 8;
        bRowOff[np] = STG_A_OFF + n * 128;
        bR7[np] = n & 7;
    }

    float acc[4][4][4];
    #pragma unroll
    for (int i = 0; i < 4; i++)
        #pragma unroll
        for (int j = 0; j < 4; j++)
            #pragma unroll
            for (int q = 0; q < 4; q++) acc[i][j][q] = 0.f;

    auto load_stage = [&](int step) {
        const int stage = step & (GSTAGES - 1);
        const int pass = step / kiters;
        const int i = step - pass * kiters;
        const __nv_bfloat16* Ap = (pass == 2) ? Alo : Ahi;
        const __nv_bfloat16* Bp = (pass == 1) ? Blo : Bhi;
        const uint32_t base = sb + stage * STG_BYTES;
        const size_t gk = (size_t)i * 64 + jA * 8;
        #pragma unroll
        for (int q = 0; q < 8; q++) {
            int r = r0 + 16 * q;
            cp_async16(base + dstA[q], Ap + (size_t)(m0 + r) * KPAD + gk);
        }
        #pragma unroll
        for (int q = 0; q < 4; q++) {
            int r = r0 + 16 * q;
            cp_async16(base + dstB[q], Bp + (size_t)(n0 + r) * KPAD + gk);
        }
        CP_COMMIT();
    };

    load_stage(0);
    load_stage(1);
    load_stage(2);

    for (int step = 0; step < total; step++) {
        CP_WAIT(2);
        __syncthreads();
        if (step + 3 < total) load_stage(step + 3);

        const uint32_t base = sb + (step & (GSTAGES - 1)) * STG_BYTES;
        #pragma unroll
        for (int k16 = 0; k16 < 4; k16++) {
            uint32_t af[4][4];
            #pragma unroll
            for (int mt = 0; mt < 4; mt++)
                ldmx4(af[mt], base + aRowOff[mt] + ((((k16 * 2 + csA) ^ aR7[mt])) << 4));
            uint32_t bf[2][4];
            #pragma unroll
            for (int np = 0; np < 2; np++)
                ldmx4(bf[np], base + bRowOff[np] + ((((k16 * 2 + csB) ^ bR7[np])) << 4));
            #pragma unroll
            for (int mt = 0; mt < 4; mt++)
                #pragma unroll
                for (int nt = 0; nt < 4; nt++)
                    mma_bf16(acc[mt][nt], af[mt], &bf[nt >> 1][(nt & 1) * 2]);
        }
        __syncthreads();
    }

    // ---- epilogue: bias + exact GELU, fp32 out ----
    #pragma unroll
    for (int mt = 0; mt < 4; mt++) {
        int row = m0 + warpM * 64 + mt * 16 + (lane >> 2);
        #pragma unroll
        for (int nt = 0; nt < 4; nt++) {
            int col = n0 + warpN * 32 + nt * 8 + (lane & 3) * 2;
            float b0 = __ldg(bias + col), b1 = __ldg(bias + col + 1);
            float2 v0, v1;
            v0.x = gelu_exact(acc[mt][nt][0] + b0);
            v0.y = gelu_exact(acc[mt][nt][1] + b1);
            v1.x = gelu_exact(acc[mt][nt][2] + b0);
            v1.y = gelu_exact(acc[mt][nt][3] + b1);
            *(float2*)(C + (size_t)row * H_ + col) = v0;
            *(float2*)(C + (size_t)(row + 8) * H_ + col) = v1;
        }
    }
}

// ---------------------------------------------------------------------------
// proposal_logits = hidden @ W_prop + b   (one warp per row)
// ---------------------------------------------------------------------------
__global__ void proposal_kernel(const float* __restrict__ hidden,
                                const float* __restrict__ W_prop,
                                const float* __restrict__ b_prop,
                                float* __restrict__ out) {
    __shared__ float sW[H_ * N_BIO];
    for (int i = threadIdx.x; i < H_ * N_BIO; i += blockDim.x) sW[i] = W_prop[i];
    __syncthreads();
    int warp = threadIdx.x >> 5, lane = threadIdx.x & 31;
    int row = blockIdx.x * 8 + warp;
    if (row >= B_ * S_) return;
    const float* h = hidden + (size_t)row * H_;
    float a0 = 0.f, a1 = 0.f, a2 = 0.f;
    for (int j = lane; j < H_; j += 32) {
        float hv = h[j];
        a0 += hv * sW[j * 3 + 0];
        a1 += hv * sW[j * 3 + 1];
        a2 += hv * sW[j * 3 + 2];
    }
    #pragma unroll
    for (int off = 16; off; off >>= 1) {
        a0 += __shfl_xor_sync(0xffffffffu, a0, off);
        a1 += __shfl_xor_sync(0xffffffffu, a1, off);
        a2 += __shfl_xor_sync(0xffffffffu, a2, off);
    }
    if (lane == 0) {
        out[row * 3 + 0] = a0 + b_prop[0];
        out[row * 3 + 1] = a1 + b_prop[1];
        out[row * 3 + 2] = a2 + b_prop[2];
    }
}

// ---------------------------------------------------------------------------
// span reps -> bf16 hi/lo directly (one block per span)
// ---------------------------------------------------------------------------
__global__ void span_rep_kernel(const float* __restrict__ hidden,
                                const int* __restrict__ spans,
                                const float* __restrict__ width_emb) {
    int row = blockIdx.x;
    int b = row >> 9;
    int s = spans[row * 2 + 0];
    int e = spans[row * 2 + 1];
    int w = e - s + 1;
    float inv_w = 1.0f / (float)w;
    const float* hb = hidden + (size_t)b * S_ * H_;
    __nv_bfloat16* hi = g_Ahi + (size_t)row * KPAD;
    __nv_bfloat16* lo = g_Alo + (size_t)row * KPAD;

    for (int i = threadIdx.x; i < H_; i += blockDim.x) {
        float sh = hb[(size_t)s * H_ + i];
        float eh = hb[(size_t)e * H_ + i];
        float acc = 0.f;
        for (int q = s; q <= e; q++) acc += hb[(size_t)q * H_ + i];
        bsplit(sh, hi + i, lo + i);
        bsplit(eh, hi + H_ + i, lo + H_ + i);
        bsplit(acc * inv_w, hi + 2 * H_ + i, lo + 2 * H_ + i);
    }
    int wc = w < 63 ? w : 63;
    for (int i = threadIdx.x; i < WEMB_D; i += blockDim.x)
        bsplit(width_emb[wc * WEMB_D + i], hi + 3 * H_ + i, lo + 3 * H_ + i);
}

// ---------------------------------------------------------------------------
// transpose + bf16 split:  W[k][768] (k < Klen) -> out_hi/lo [768][KPAD]
// ---------------------------------------------------------------------------
__global__ void transpose_split(const float* __restrict__ W, int Klen,
                                __nv_bfloat16* __restrict__ out_hi,
                                __nv_bfloat16* __restrict__ out_lo) {
    __shared__ float tile[32][33];
    int nb = blockIdx.x * 32, kb = blockIdx.y * 32;
    int x = nb + threadIdx.x;
    #pragma unroll
    for (int i = 0; i < 4; i++) {
        int k = kb + threadIdx.y + i * 8;
        tile[threadIdx.y + i * 8][threadIdx.x] = (k < Klen) ? W[(size_t)k * H_ + x] : 0.f;
    }
    __syncthreads();
    int kk = kb + threadIdx.x;
    #pragma unroll
    for (int i = 0; i < 4; i++) {
        int n = nb + threadIdx.y + i * 8;
        float v = tile[threadIdx.x][threadIdx.y + i * 8];
        bsplit(v, out_hi + (size_t)n * KPAD + kk, out_lo + (size_t)n * KPAD + kk);
    }
}

// ---------------------------------------------------------------------------
// type head: logits = g_t @ W_t2 + b; softmax probs -> A_hi/A_lo cols 2688..2705
// ---------------------------------------------------------------------------
__global__ void type_head_kernel(const float* __restrict__ W_t2,
                                 const float* __restrict__ b_t2,
                                 float* __restrict__ out_logits) {
    extern __shared__ float sW[];   // 768*18
    for (int i = threadIdx.x; i < H_ * N_TYPE; i += blockDim.x) sW[i] = W_t2[i];
    __syncthreads();
    int warp = threadIdx.x >> 5, lane = threadIdx.x & 31;
    int row = blockIdx.x * 8 + warp;
    if (row >= NROW) return;
    const float* t = g_t + (size_t)row * H_;
    float acc[N_TYPE];
    #pragma unroll
    for (int c = 0; c < N_TYPE; c++) acc[c] = 0.f;
    for (int j = lane; j < H_; j += 32) {
        float tv = t[j];
        const float* wr = sW + j * N_TYPE;
        #pragma unroll
        for (int c = 0; c < N_TYPE; c++) acc[c] = fmaf(tv, wr[c], acc[c]);
    }
    #pragma unroll
    for (int c = 0; c < N_TYPE; c++)
        #pragma unroll
        for (int off = 16; off; off >>= 1)
            acc[c] += __shfl_xor_sync(0xffffffffu, acc[c], off);
    if (lane == 0) {
        float logit[N_TYPE], mx = -1e30f;
        #pragma unroll
        for (int c = 0; c < N_TYPE; c++) { logit[c] = acc[c] + b_t2[c]; mx = fmaxf(mx, logit[c]); }
        float sum = 0.f, ex[N_TYPE];
        #pragma unroll
        for (int c = 0; c < N_TYPE; c++) { ex[c] = expf(logit[c] - mx); sum += ex[c]; }
        float inv = 1.0f / sum;
        __nv_bfloat16* hi = g_Ahi + (size_t)row * KPAD + SPAN_DIM;
        __nv_bfloat16* lo = g_Alo + (size_t)row * KPAD + SPAN_DIM;
        #pragma unroll
        for (int c = 0; c < N_TYPE; c++) {
            out_logits[row * N_TYPE + c] = logit[c];
            bsplit(ex[c] * inv, hi + c, lo + c);
        }
    }
}

// ---------------------------------------------------------------------------
// sensitivity head
// ---------------------------------------------------------------------------
__global__ void sens_head_kernel(const float* __restrict__ W_s2,
                                 const float* __restrict__ b_s2,
                                 float* __restrict__ out_logits) {
    __shared__ float sW[H_ * N_SENS];
    for (int i = threadIdx.x; i < H_ * N_SENS; i += blockDim.x) sW[i] = W_s2[i];
    __syncthreads();
    int warp = threadIdx.x >> 5, lane = threadIdx.x & 31;
    int row = blockIdx.x * 8 + warp;
    if (row >= NROW) return;
    const float* s = g_s + (size_t)row * H_;
    float acc[N_SENS];
    #pragma unroll
    for (int c = 0; c < N_SENS; c++) acc[c] = 0.f;
    for (int j = lane; j < H_; j += 32) {
        float sv = s[j];
        const float* wr = sW + j * N_SENS;
        #pragma unroll
        for (int c = 0; c < N_SENS; c++) acc[c] = fmaf(sv, wr[c], acc[c]);
    }
    #pragma unroll
    for (int c = 0; c < N_SENS; c++)
        #pragma unroll
        for (int off = 16; off; off >>= 1)
            acc[c] += __shfl_xor_sync(0xffffffffu, acc[c], off);
    if (lane == 0)
        #pragma unroll
        for (int c = 0; c < N_SENS; c++)
            out_logits[row * N_SENS + c] = acc[c] + b_s2[c];
}

// ---------------------------------------------------------------------------
// Launch
// ---------------------------------------------------------------------------
extern "C" void kernel_launch(void* const* d_in, const int* in_sizes, int n_in,
                              void* d_out, int out_size) {
    const float* hidden    = (const float*)d_in[0];
    const int*   spans     = (const int*)d_in[1];
    const float* width_emb = (const float*)d_in[2];
    const float* W_prop    = (const float*)d_in[3];
    const float* b_prop    = (const float*)d_in[4];
    const float* W_t1      = (const float*)d_in[5];
    const float* b_t1      = (const float*)d_in[6];
    const float* W_t2      = (const float*)d_in[7];
    const float* b_t2      = (const float*)d_in[8];
    const float* W_s1      = (const float*)d_in[9];
    const float* b_s1      = (const float*)d_in[10];
    const float* W_s2      = (const float*)d_in[11];
    const float* b_s2      = (const float*)d_in[12];

    float* out_prop = (float*)d_out;
    float* out_type = out_prop + (size_t)B_ * S_ * N_BIO;
    float* out_sens = out_type + (size_t)NROW * N_TYPE;

    void *ahi, *alo, *bt1h, *bt1l, *bs1h, *bs1l, *tbuf, *sbuf;
    cudaGetSymbolAddress(&ahi, g_Ahi);
    cudaGetSymbolAddress(&alo, g_Alo);
    cudaGetSymbolAddress(&bt1h, g_Bt1hi);
    cudaGetSymbolAddress(&bt1l, g_Bt1lo);
    cudaGetSymbolAddress(&bs1h, g_Bs1hi);
    cudaGetSymbolAddress(&bs1l, g_Bs1lo);
    cudaGetSymbolAddress(&tbuf, g_t);
    cudaGetSymbolAddress(&sbuf, g_s);

    cudaFuncSetAttribute(mma_gemm, cudaFuncAttributeMaxDynamicSharedMemorySize, GEMM_SMEM);
    cudaFuncSetAttribute(type_head_kernel, cudaFuncAttributeMaxDynamicSharedMemorySize,
                         H_ * N_TYPE * (int)sizeof(float));

    // 1. proposal head
    proposal_kernel<<<(B_ * S_) / 8, 256>>>(hidden, W_prop, b_prop, out_prop);
    // 2. span reps -> bf16 hi/lo
    span_rep_kernel<<<NROW, 256>>>(hidden, spans, width_emb);
    // 3. weight transposes (bf16 split)
    {
        dim3 blk(32, 8);
        dim3 g1(H_ / 32, (SPAN_DIM + 31) / 32);
        transpose_split<<<g1, blk>>>(W_t1, SPAN_DIM, (__nv_bfloat16*)bt1h, (__nv_bfloat16*)bt1l);
        dim3 g2(H_ / 32, (SIN_DIM + 31) / 32);
        transpose_split<<<g2, blk>>>(W_s1, SIN_DIM, (__nv_bfloat16*)bs1h, (__nv_bfloat16*)bs1l);
    }
    // 4. GEMM1: g_t = gelu(rep @ W_t1 + b_t1)
    {
        dim3 grid(H_ / BNg, NROW / BMg);
        mma_gemm<<<grid, 128, GEMM_SMEM>>>((const __nv_bfloat16*)ahi, (const __nv_bfloat16*)alo,
                                           (const __nv_bfloat16*)bt1h, (const __nv_bfloat16*)bt1l,
                                           b_t1, (float*)tbuf, KITERS1);
    }
    // 5. type head (+ probs appended into A hi/lo)
    type_head_kernel<<<NROW / 8, 256, H_ * N_TYPE * (int)sizeof(float)>>>(W_t2, b_t2, out_type);
    // 6. GEMM2: g_s = gelu([rep|probs] @ W_s1 + b_s1)
    {
        dim3 grid(H_ / BNg, NROW / BMg);
        mma_gemm<<<grid, 128, GEMM_SMEM>>>((const __nv_bfloat16*)ahi, (const __nv_bfloat16*)alo,
                                           (const __nv_bfloat16*)bs1h, (const __nv_bfloat16*)bs1l,
                                           b_s1, (float*)sbuf, KITERS2);
    }
    // 7. sensitivity head
    sens_head_kernel<<<NROW / 8, 256>>>(W_s2, b_s2, out_sens);
}